// round 2
// baseline (speedup 1.0000x reference)
#include <cuda_runtime.h>
#include <cuda_bf16.h>
#include <cstddef>

#define BATCH 16
#define CH    512
#define S     128

// Deterministic per-row partials (no allocation: device globals)
__device__ float g_ww_part[BATCH * S * S];   // [b][h][w'] 1 MB
__device__ float g_hw_part[BATCH * S * 8];   // [b][h][kh] (5 used, pad 8)

// ---------------------------------------------------------------------------
// K1: one block per (b, h) row. Streams x[b, :, h, :] (256 KB), computes the
// 2-channel 1x1-conv row, then the ww 5-tap correlation and hw dot partials.
// ---------------------------------------------------------------------------
__global__ __launch_bounds__(128, 16) void swa_k1(
    const float4* __restrict__ x4,
    const float*  __restrict__ wconv,   // [2,512]
    const float*  __restrict__ www,     // [1,2,128,5]
    const float*  __restrict__ whw)     // [1,2,5,128]
{
    __shared__ float s_wc[2][CH];          // 4 KB
    __shared__ float s_red[4][2][S];       // 4 KB  (channel-group partials)
    __shared__ float s_x2[2][S];           // 1 KB
    __shared__ float s_hwred[4][5];

    const int h = blockIdx.x;
    const int b = blockIdx.y;
    const int t = threadIdx.x;

    // load 1x1-conv weights [2,512] into shared
    #pragma unroll
    for (int i = t; i < 2 * CH; i += 128) s_wc[i >> 9][i & 511] = wconv[i];
    __syncthreads();

    // channel-group layout: 4 groups of 128 channels, 32 float4 positions per row
    const int w4 = t & 31;      // float4 position within row (w = w4*4..+3)
    const int cg = t >> 5;      // channel group 0..3

    // base index in float4 units: ((b*CH + cg*128)*S + h)*S/4 + w4
    size_t base4 = ((size_t)(b * CH + cg * 128) * S + (size_t)h) * (S / 4) + (size_t)w4;

    float a00 = 0.f, a01 = 0.f, a02 = 0.f, a03 = 0.f;
    float a10 = 0.f, a11 = 0.f, a12 = 0.f, a13 = 0.f;

    #pragma unroll 8
    for (int c = 0; c < 128; c++) {
        float4 v = __ldg(&x4[base4 + (size_t)c * (S * S / 4)]);
        float w0 = s_wc[0][cg * 128 + c];
        float w1 = s_wc[1][cg * 128 + c];
        a00 += v.x * w0; a01 += v.y * w0; a02 += v.z * w0; a03 += v.w * w0;
        a10 += v.x * w1; a11 += v.y * w1; a12 += v.z * w1; a13 += v.w * w1;
    }

    s_red[cg][0][w4 * 4 + 0] = a00;
    s_red[cg][0][w4 * 4 + 1] = a01;
    s_red[cg][0][w4 * 4 + 2] = a02;
    s_red[cg][0][w4 * 4 + 3] = a03;
    s_red[cg][1][w4 * 4 + 0] = a10;
    s_red[cg][1][w4 * 4 + 1] = a11;
    s_red[cg][1][w4 * 4 + 2] = a12;
    s_red[cg][1][w4 * 4 + 3] = a13;
    __syncthreads();

    // reduce 4 channel-groups -> x2 row (each thread handles w=t for both o)
    {
        float s0 = 0.f, s1 = 0.f;
        #pragma unroll
        for (int g = 0; g < 4; g++) { s0 += s_red[g][0][t]; s1 += s_red[g][1][t]; }
        s_x2[0][t] = s0;
        s_x2[1][t] = s1;
    }
    __syncthreads();

    // --- hw branch: 5 dot products of the row with w_hw[o][kh][:] ---
    {
        const float x20 = s_x2[0][t];
        const float x21 = s_x2[1][t];
        float p[5];
        #pragma unroll
        for (int kh = 0; kh < 5; kh++)
            p[kh] = x20 * __ldg(&whw[kh * S + t]) + x21 * __ldg(&whw[(5 + kh) * S + t]);
        #pragma unroll
        for (int off = 16; off > 0; off >>= 1) {
            #pragma unroll
            for (int kh = 0; kh < 5; kh++)
                p[kh] += __shfl_down_sync(0xffffffffu, p[kh], off);
        }
        if ((t & 31) == 0) {
            #pragma unroll
            for (int kh = 0; kh < 5; kh++) s_hwred[t >> 5][kh] = p[kh];
        }
    }

    // --- ww branch: 5-tap correlation along w with w_ww[o][h][:] ---
    {
        float acc = 0.f;
        #pragma unroll
        for (int kw = 0; kw < 5; kw++) {
            int wi = t - 2 + kw;
            if (wi >= 0 && wi < S)
                acc += s_x2[0][wi] * __ldg(&www[h * 5 + kw])
                     + s_x2[1][wi] * __ldg(&www[(S + h) * 5 + kw]);
        }
        g_ww_part[((size_t)b * S + h) * S + t] = acc;
    }
    __syncthreads();

    if (t < 5) {
        g_hw_part[((b * S + h) << 3) + t] =
            s_hwred[0][t] + s_hwred[1][t] + s_hwred[2][t] + s_hwred[3][t];
    }
}

// ---------------------------------------------------------------------------
// K2: one block per batch. Reduce partials over h, linear + sigmoid for both
// branches, then write the [128,128] outer product.
// ---------------------------------------------------------------------------
__global__ __launch_bounds__(256) void swa_k2(
    const float* __restrict__ wwlw,   // [128,128]
    const float* __restrict__ wwlb,   // [128]
    const float* __restrict__ hwlw,   // [128,128]
    const float* __restrict__ hwlb,   // [128]
    float* __restrict__ out)          // [B,128,128]
{
    __shared__ __align__(16) float s_raw[2][S];  // 0: ww_raw, 1: hw_raw
    __shared__ __align__(16) float s_sig[2][S];  // 0: ww_sig, 1: hw_sig

    const int b = blockIdx.x;
    const int t = threadIdx.x;

    if (t < S) {
        // ww_raw[w'] = sum_h ww_part[b][h][w']
        float s = 0.f;
        const float* p = g_ww_part + (size_t)b * S * S + t;
        #pragma unroll 8
        for (int hh = 0; hh < S; hh++) s += p[hh * S];
        s_raw[0][t] = s;
    } else {
        // hw_raw[h'] = sum_kh hw_part[b][h'-2+kh][kh]  (bounds-checked)
        const int hp = t - S;
        float s = 0.f;
        #pragma unroll
        for (int kh = 0; kh < 5; kh++) {
            int hh = hp - 2 + kh;
            if (hh >= 0 && hh < S) s += g_hw_part[((b * S + hh) << 3) + kh];
        }
        s_raw[1][hp] = s;
    }
    __syncthreads();

    // Linear + sigmoid: threads 0..127 -> ww, 128..255 -> hw
    {
        const int which = t >> 7;
        const int i = t & 127;
        const float* W = which ? hwlw : wwlw;
        const float* bia = which ? hwlb : wwlb;
        float acc = bia[i];
        #pragma unroll 8
        for (int j = 0; j < S; j++) acc += s_raw[which][j] * W[i * S + j];
        s_sig[which][i] = 1.f / (1.f + expf(-acc));
    }
    __syncthreads();

    // Outer product: out[b][h][w] = hw_sig[h] * ww_sig[w]
    float4* o4 = (float4*)(out + (size_t)b * S * S);
    const float4* ww4 = (const float4*)&s_sig[0][0];
    for (int i = t; i < S * S / 4; i += 256) {
        int hh = i >> 5;       // 32 float4 per row
        int wq = i & 31;
        float hv = s_sig[1][hh];
        float4 wv = ww4[wq];
        o4[i] = make_float4(hv * wv.x, hv * wv.y, hv * wv.z, hv * wv.w);
    }
}

extern "C" void kernel_launch(void* const* d_in, const int* in_sizes, int n_in,
                              void* d_out, int out_size)
{
    const float* x     = (const float*)d_in[0];
    const float* wconv = (const float*)d_in[1];
    const float* www   = (const float*)d_in[2];
    const float* whw   = (const float*)d_in[3];
    const float* wwlw  = (const float*)d_in[4];
    const float* wwlb  = (const float*)d_in[5];
    const float* hwlw  = (const float*)d_in[6];
    const float* hwlb  = (const float*)d_in[7];
    float* out = (float*)d_out;

    dim3 g1(S, BATCH);
    swa_k1<<<g1, 128>>>((const float4*)x, wconv, www, whw);
    swa_k2<<<BATCH, 256>>>(wwlw, wwlb, hwlw, hwlb, out);
}

// round 3
// speedup vs baseline: 1.1297x; 1.1297x over previous
#include <cuda_runtime.h>
#include <cuda_bf16.h>
#include <cstddef>

#define BATCH 16
#define CH    512
#define S     128

// Per-batch branch accumulators (atomically reduced in K1's epilogue)
__device__ float g_ww_raw[BATCH * S];   // [b][w'] pre-linear ww vector
__device__ float g_hw_raw[BATCH * S];   // [b][h'] pre-linear hw vector

// ---------------------------------------------------------------------------
// K0: zero the accumulators (must run before K1 every replay)
// ---------------------------------------------------------------------------
__global__ void swa_zero()
{
    int i = blockIdx.x * 1024 + threadIdx.x;   // 0..2047
    g_ww_raw[i] = 0.f;
    g_hw_raw[i] = 0.f;
}

// ---------------------------------------------------------------------------
// K1: one block per (b, h) row. Streams x[b, :, h, :] (256 KB), computes the
// 2-channel 1x1-conv row, then atomically accumulates the ww 5-tap
// correlation and hw dot contributions into the per-batch vectors.
// ---------------------------------------------------------------------------
__global__ __launch_bounds__(128, 16) void swa_k1(
    const float4* __restrict__ x4,
    const float*  __restrict__ wconv,   // [2,512]
    const float*  __restrict__ www,     // [1,2,128,5]
    const float*  __restrict__ whw)     // [1,2,5,128]
{
    __shared__ float s_wc[2][CH];          // 4 KB
    __shared__ float s_red[4][2][S];       // 4 KB  (channel-group partials)
    __shared__ float s_x2[2][S];           // 1 KB
    __shared__ float s_hwred[4][5];

    const int h = blockIdx.x;
    const int b = blockIdx.y;
    const int t = threadIdx.x;

    // load 1x1-conv weights [2,512] into shared
    #pragma unroll
    for (int i = t; i < 2 * CH; i += 128) s_wc[i >> 9][i & 511] = wconv[i];
    __syncthreads();

    // channel-group layout: 4 groups of 128 channels, 32 float4 positions per row
    const int w4 = t & 31;      // float4 position within row (w = w4*4..+3)
    const int cg = t >> 5;      // channel group 0..3

    size_t base4 = ((size_t)(b * CH + cg * 128) * S + (size_t)h) * (S / 4) + (size_t)w4;

    float a00 = 0.f, a01 = 0.f, a02 = 0.f, a03 = 0.f;
    float a10 = 0.f, a11 = 0.f, a12 = 0.f, a13 = 0.f;

    #pragma unroll 8
    for (int c = 0; c < 128; c++) {
        float4 v = __ldg(&x4[base4 + (size_t)c * (S * S / 4)]);
        float w0 = s_wc[0][cg * 128 + c];
        float w1 = s_wc[1][cg * 128 + c];
        a00 += v.x * w0; a01 += v.y * w0; a02 += v.z * w0; a03 += v.w * w0;
        a10 += v.x * w1; a11 += v.y * w1; a12 += v.z * w1; a13 += v.w * w1;
    }

    s_red[cg][0][w4 * 4 + 0] = a00;
    s_red[cg][0][w4 * 4 + 1] = a01;
    s_red[cg][0][w4 * 4 + 2] = a02;
    s_red[cg][0][w4 * 4 + 3] = a03;
    s_red[cg][1][w4 * 4 + 0] = a10;
    s_red[cg][1][w4 * 4 + 1] = a11;
    s_red[cg][1][w4 * 4 + 2] = a12;
    s_red[cg][1][w4 * 4 + 3] = a13;
    __syncthreads();

    // reduce 4 channel-groups -> x2 row
    {
        float s0 = 0.f, s1 = 0.f;
        #pragma unroll
        for (int g = 0; g < 4; g++) { s0 += s_red[g][0][t]; s1 += s_red[g][1][t]; }
        s_x2[0][t] = s0;
        s_x2[1][t] = s1;
    }
    __syncthreads();

    // --- hw branch: 5 dot products of the row with w_hw[o][kh][:] ---
    {
        const float x20 = s_x2[0][t];
        const float x21 = s_x2[1][t];
        float p[5];
        #pragma unroll
        for (int kh = 0; kh < 5; kh++)
            p[kh] = x20 * __ldg(&whw[kh * S + t]) + x21 * __ldg(&whw[(5 + kh) * S + t]);
        #pragma unroll
        for (int off = 16; off > 0; off >>= 1) {
            #pragma unroll
            for (int kh = 0; kh < 5; kh++)
                p[kh] += __shfl_down_sync(0xffffffffu, p[kh], off);
        }
        if ((t & 31) == 0) {
            #pragma unroll
            for (int kh = 0; kh < 5; kh++) s_hwred[t >> 5][kh] = p[kh];
        }
    }

    // --- ww branch: 5-tap correlation along w, atomically accumulated ---
    {
        float acc = 0.f;
        #pragma unroll
        for (int kw = 0; kw < 5; kw++) {
            int wi = t - 2 + kw;
            if (wi >= 0 && wi < S)
                acc += s_x2[0][wi] * __ldg(&www[h * 5 + kw])
                     + s_x2[1][wi] * __ldg(&www[(S + h) * 5 + kw]);
        }
        atomicAdd(&g_ww_raw[b * S + t], acc);
    }
    __syncthreads();

    // hw: row h contributes p[kh] to hw_raw[h + 2 - kh]
    if (t < 5) {
        float v = s_hwred[0][t] + s_hwred[1][t] + s_hwred[2][t] + s_hwred[3][t];
        int hp = h + 2 - t;
        if (hp >= 0 && hp < S)
            atomicAdd(&g_hw_raw[b * S + hp], v);
    }
}

// ---------------------------------------------------------------------------
// K2: one block per batch. Linear + sigmoid for both branches (coalesced,
// warp-cooperative with shared transpose reduction), then outer product.
// ---------------------------------------------------------------------------
__global__ __launch_bounds__(256) void swa_k2(
    const float* __restrict__ wwlw,   // [128,128]
    const float* __restrict__ wwlb,   // [128]
    const float* __restrict__ hwlw,   // [128,128]
    const float* __restrict__ hwlb,   // [128]
    float* __restrict__ out)          // [B,128,128]
{
    __shared__ __align__(16) float s_raw[2][S];        // 0: ww_raw, 1: hw_raw
    __shared__ __align__(16) float s_sig[2][S];        // 0: ww_sig, 1: hw_sig
    __shared__ float s_part[8][32][33];                // warp-transpose buffer (~33.8 KB)

    const int b = blockIdx.x;
    const int t = threadIdx.x;
    const int wp = t >> 5;       // warp 0..7
    const int ln = t & 31;

    if (t < S)        s_raw[0][t]      = g_ww_raw[b * S + t];
    else              s_raw[1][t - S]  = g_hw_raw[b * S + (t - S)];
    __syncthreads();

    // Warps 0-3: ww rows [wp*32, wp*32+32). Warps 4-7: hw rows [(wp-4)*32, ...).
    {
        const int which   = wp >> 2;
        const int rowbase = (wp & 3) * 32;
        const float* W    = which ? hwlw : wwlw;
        const float* vec  = s_raw[which];

        float v0 = vec[ln], v1 = vec[ln + 32], v2 = vec[ln + 64], v3 = vec[ln + 96];

        #pragma unroll
        for (int r = 0; r < 32; r++) {
            const float* Wr = W + (rowbase + r) * S;
            float p = Wr[ln] * v0 + Wr[ln + 32] * v1 + Wr[ln + 64] * v2 + Wr[ln + 96] * v3;
            s_part[wp][r][ln] = p;
        }
    }
    __syncthreads();

    // Thread t reduces its own row: output index = t (t<128: ww, else hw)
    {
        const int which = t >> 7;
        const int i = t & 127;
        float acc = which ? hwlb[i] : wwlb[i];
        #pragma unroll
        for (int l = 0; l < 32; l++) acc += s_part[wp][ln][l];
        s_sig[which][i] = 1.f / (1.f + expf(-acc));
    }
    __syncthreads();

    // Outer product: out[b][h][w] = hw_sig[h] * ww_sig[w]
    float4* o4 = (float4*)(out + (size_t)b * S * S);
    const float4* ww4 = (const float4*)&s_sig[0][0];
    #pragma unroll 4
    for (int i = t; i < S * S / 4; i += 256) {
        int hh = i >> 5;
        int wq = i & 31;
        float hv = s_sig[1][hh];
        float4 wv = ww4[wq];
        o4[i] = make_float4(hv * wv.x, hv * wv.y, hv * wv.z, hv * wv.w);
    }
}

extern "C" void kernel_launch(void* const* d_in, const int* in_sizes, int n_in,
                              void* d_out, int out_size)
{
    const float* x     = (const float*)d_in[0];
    const float* wconv = (const float*)d_in[1];
    const float* www   = (const float*)d_in[2];
    const float* whw   = (const float*)d_in[3];
    const float* wwlw  = (const float*)d_in[4];
    const float* wwlb  = (const float*)d_in[5];
    const float* hwlw  = (const float*)d_in[6];
    const float* hwlb  = (const float*)d_in[7];
    float* out = (float*)d_out;

    swa_zero<<<2, 1024>>>();
    dim3 g1(S, BATCH);
    swa_k1<<<g1, 128>>>((const float4*)x, wconv, www, whw);
    swa_k2<<<BATCH, 256>>>(wwlw, wwlb, hwlw, hwlb, out);
}

// round 4
// speedup vs baseline: 1.1831x; 1.0473x over previous
#include <cuda_runtime.h>
#include <cuda_bf16.h>
#include <cstddef>

#define BATCH 16
#define CH    512
#define S     128

// Per-batch branch accumulators. Zero-initialized at load; K2 re-zeroes them
// after consuming, so they are always zero on entry to kernel_launch.
__device__ float g_ww_raw[BATCH * S];   // [b][w'] pre-linear ww vector
__device__ float g_hw_raw[BATCH * S];   // [b][h'] pre-linear hw vector

// ---------------------------------------------------------------------------
// K1: one block per (b, h) row. Streams x[b, :, h, :] (256 KB), computes the
// 2-channel 1x1-conv row, then atomically accumulates the ww 5-tap
// correlation and hw dot contributions into the per-batch vectors.
// ---------------------------------------------------------------------------
__global__ __launch_bounds__(128, 16) void swa_k1(
    const float4* __restrict__ x4,
    const float*  __restrict__ wconv,   // [2,512]
    const float*  __restrict__ www,     // [1,2,128,5]
    const float*  __restrict__ whw)     // [1,2,5,128]
{
    __shared__ float s_wc[2][CH];          // 4 KB
    __shared__ float s_red[4][2][S];       // 4 KB  (channel-group partials)
    __shared__ float s_x2[2][S];           // 1 KB
    __shared__ float s_hwred[4][5];

    const int h = blockIdx.x;
    const int b = blockIdx.y;
    const int t = threadIdx.x;

    // load 1x1-conv weights [2,512] into shared
    #pragma unroll
    for (int i = t; i < 2 * CH; i += 128) s_wc[i >> 9][i & 511] = wconv[i];
    __syncthreads();

    // channel-group layout: 4 groups of 128 channels, 32 float4 positions/row
    const int w4 = t & 31;      // float4 position within row (w = w4*4..+3)
    const int cg = t >> 5;      // channel group 0..3

    size_t base4 = ((size_t)(b * CH + cg * 128) * S + (size_t)h) * (S / 4) + (size_t)w4;

    float a00 = 0.f, a01 = 0.f, a02 = 0.f, a03 = 0.f;
    float a10 = 0.f, a11 = 0.f, a12 = 0.f, a13 = 0.f;

    #pragma unroll 8
    for (int c = 0; c < 128; c++) {
        float4 v = __ldg(&x4[base4 + (size_t)c * (S * S / 4)]);
        float w0 = s_wc[0][cg * 128 + c];
        float w1 = s_wc[1][cg * 128 + c];
        a00 += v.x * w0; a01 += v.y * w0; a02 += v.z * w0; a03 += v.w * w0;
        a10 += v.x * w1; a11 += v.y * w1; a12 += v.z * w1; a13 += v.w * w1;
    }

    s_red[cg][0][w4 * 4 + 0] = a00;
    s_red[cg][0][w4 * 4 + 1] = a01;
    s_red[cg][0][w4 * 4 + 2] = a02;
    s_red[cg][0][w4 * 4 + 3] = a03;
    s_red[cg][1][w4 * 4 + 0] = a10;
    s_red[cg][1][w4 * 4 + 1] = a11;
    s_red[cg][1][w4 * 4 + 2] = a12;
    s_red[cg][1][w4 * 4 + 3] = a13;
    __syncthreads();

    // reduce 4 channel-groups -> x2 row
    {
        float s0 = 0.f, s1 = 0.f;
        #pragma unroll
        for (int g = 0; g < 4; g++) { s0 += s_red[g][0][t]; s1 += s_red[g][1][t]; }
        s_x2[0][t] = s0;
        s_x2[1][t] = s1;
    }
    __syncthreads();

    // --- hw branch: 5 dot products of the row with w_hw[o][kh][:] ---
    {
        const float x20 = s_x2[0][t];
        const float x21 = s_x2[1][t];
        float p[5];
        #pragma unroll
        for (int kh = 0; kh < 5; kh++)
            p[kh] = x20 * __ldg(&whw[kh * S + t]) + x21 * __ldg(&whw[(5 + kh) * S + t]);
        #pragma unroll
        for (int off = 16; off > 0; off >>= 1) {
            #pragma unroll
            for (int kh = 0; kh < 5; kh++)
                p[kh] += __shfl_down_sync(0xffffffffu, p[kh], off);
        }
        if ((t & 31) == 0) {
            #pragma unroll
            for (int kh = 0; kh < 5; kh++) s_hwred[t >> 5][kh] = p[kh];
        }
    }

    // --- ww branch: 5-tap correlation along w, atomically accumulated ---
    {
        float acc = 0.f;
        #pragma unroll
        for (int kw = 0; kw < 5; kw++) {
            int wi = t - 2 + kw;
            if (wi >= 0 && wi < S)
                acc += s_x2[0][wi] * __ldg(&www[h * 5 + kw])
                     + s_x2[1][wi] * __ldg(&www[(S + h) * 5 + kw]);
        }
        atomicAdd(&g_ww_raw[b * S + t], acc);
    }
    __syncthreads();

    // hw: row h contributes p[kh] to hw_raw[h + 2 - kh]
    if (t < 5) {
        float v = s_hwred[0][t] + s_hwred[1][t] + s_hwred[2][t] + s_hwred[3][t];
        int hp = h + 2 - t;
        if (hp >= 0 && hp < S)
            atomicAdd(&g_hw_raw[b * S + hp], v);
    }
}

// ---------------------------------------------------------------------------
// K2: one block per batch. Consumes + re-zeroes the raw vectors, linear +
// sigmoid for both branches (warp-cooperative, shuffle reduction), then
// writes the [128,128] outer product.
// ---------------------------------------------------------------------------
__global__ __launch_bounds__(256) void swa_k2(
    const float* __restrict__ wwlw,   // [128,128]
    const float* __restrict__ wwlb,   // [128]
    const float* __restrict__ hwlw,   // [128,128]
    const float* __restrict__ hwlb,   // [128]
    float* __restrict__ out)          // [B,128,128]
{
    __shared__ __align__(16) float s_raw[2][S];   // 0: ww_raw, 1: hw_raw
    __shared__ __align__(16) float s_sig[2][S];   // 0: ww_sig, 1: hw_sig

    const int b = blockIdx.x;
    const int t = threadIdx.x;
    const int wp = t >> 5;       // warp 0..7
    const int ln = t & 31;

    // Load raw vectors and re-zero for the next replay (same thread, same
    // address: program-order safe; invariant restored for next launch).
    if (t < S) {
        float v = g_ww_raw[b * S + t];
        g_ww_raw[b * S + t] = 0.f;
        s_raw[0][t] = v;
    } else {
        float v = g_hw_raw[b * S + (t - S)];
        g_hw_raw[b * S + (t - S)] = 0.f;
        s_raw[1][t - S] = v;
    }
    __syncthreads();

    // Warps 0-3: ww rows [ (wp&3)*32, +32 ).  Warps 4-7: hw rows same span.
    // Each lane holds 4 vector elements; per output row: coalesced 4-term
    // partial + 5-step butterfly reduce. Lane r keeps row r's result.
    {
        const int which   = wp >> 2;
        const int rowbase = (wp & 3) * 32;
        const float* W    = which ? hwlw : wwlw;
        const float* vec  = s_raw[which];

        float v0 = vec[ln], v1 = vec[ln + 32], v2 = vec[ln + 64], v3 = vec[ln + 96];

        float myrow = 0.f;
        #pragma unroll
        for (int r = 0; r < 32; r++) {
            const float* Wr = W + (rowbase + r) * S;
            float p = Wr[ln] * v0 + Wr[ln + 32] * v1 + Wr[ln + 64] * v2 + Wr[ln + 96] * v3;
            #pragma unroll
            for (int off = 16; off > 0; off >>= 1)
                p += __shfl_xor_sync(0xffffffffu, p, off);
            if (ln == r) myrow = p;     // full reduce: every lane has the sum
        }

        const int i = rowbase + ln;
        float acc = myrow + (which ? hwlb[i] : wwlb[i]);
        s_sig[which][i] = 1.f / (1.f + expf(-acc));
    }
    __syncthreads();

    // Outer product: out[b][h][w] = hw_sig[h] * ww_sig[w]
    float4* o4 = (float4*)(out + (size_t)b * S * S);
    const float4* ww4 = (const float4*)&s_sig[0][0];
    #pragma unroll 4
    for (int i = t; i < S * S / 4; i += 256) {
        int hh = i >> 5;
        int wq = i & 31;
        float hv = s_sig[1][hh];
        float4 wv = ww4[wq];
        o4[i] = make_float4(hv * wv.x, hv * wv.y, hv * wv.z, hv * wv.w);
    }
}

extern "C" void kernel_launch(void* const* d_in, const int* in_sizes, int n_in,
                              void* d_out, int out_size)
{
    const float* x     = (const float*)d_in[0];
    const float* wconv = (const float*)d_in[1];
    const float* www   = (const float*)d_in[2];
    const float* whw   = (const float*)d_in[3];
    const float* wwlw  = (const float*)d_in[4];
    const float* wwlb  = (const float*)d_in[5];
    const float* hwlw  = (const float*)d_in[6];
    const float* hwlb  = (const float*)d_in[7];
    float* out = (float*)d_out;

    dim3 g1(S, BATCH);
    swa_k1<<<g1, 128>>>((const float4*)x, wconv, www, whw);
    swa_k2<<<BATCH, 256>>>(wwlw, wwlb, hwlw, hwlb, out);
}